// round 10
// baseline (speedup 1.0000x reference)
#include <cuda_runtime.h>
#include <cstdint>

// ---------------------------------------------------------------------------
// Problem constants
// ---------------------------------------------------------------------------
#define NB   2048
#define HID  1024
#define NH   16
#define DH   64
#define WKW  64
#define NSLOT 129
#define LOG2E 1.44269504f

// attn smem pads
#define SKP 68
#define SVP 72
#define SBP 136

// qkv gemm smem strides (floats)
#define SAS 20
#define SBS 136

// ---------------------------------------------------------------------------
// Device scratch
// ---------------------------------------------------------------------------
__device__ float g_Q[NH * NB * DH];      // [h][n][d] exact fp32
__device__ float g_K[NH * NB * DH];      // [h][n][d] tf32-rounded bits
__device__ float g_V[NH * NB * DH];      // [h][n][d] tf32-rounded bits
__device__ float g_Ak[NH * NB * NSLOT]; // scaled relative-K bias [h][n][slot]
__device__ float g_Ext[NB];             // (1-mask)*NEG_BIG*LOG2E

// ---------------------------------------------------------------------------
// Helpers
// ---------------------------------------------------------------------------
__device__ __forceinline__ unsigned f2tf(float x) {
    unsigned u;
    asm("cvt.rna.tf32.f32 %0, %1;" : "=r"(u) : "f"(x));
    return u;
}
__device__ __forceinline__ float fexp2(float x) {
    float y;
    asm("ex2.approx.ftz.f32 %0, %1;" : "=f"(y) : "f"(x));
    return y;
}
__device__ __forceinline__ void mma_tf32(float c[4], const unsigned a[4],
                                         unsigned b0, unsigned b1) {
    asm volatile(
        "mma.sync.aligned.m16n8k8.row.col.f32.tf32.tf32.f32 "
        "{%0,%1,%2,%3},{%4,%5,%6,%7},{%8,%9},{%0,%1,%2,%3};"
        : "+f"(c[0]), "+f"(c[1]), "+f"(c[2]), "+f"(c[3])
        : "r"(a[0]), "r"(a[1]), "r"(a[2]), "r"(a[3]), "r"(b0), "r"(b1));
}
__device__ __forceinline__ uint32_t smem_u32(const void* p) {
    uint32_t a;
    asm("{ .reg .u64 t; cvta.to.shared.u64 t, %1; cvt.u32.u64 %0, t; }"
        : "=r"(a) : "l"(p));
    return a;
}
__device__ __forceinline__ void cp_async16(uint32_t s, const void* g) {
    asm volatile("cp.async.cg.shared.global [%0], [%1], 16;" :: "r"(s), "l"(g));
}
__device__ __forceinline__ void cp_commit() {
    asm volatile("cp.async.commit_group;");
}
template <int N>
__device__ __forceinline__ void cp_wait() {
    asm volatile("cp.async.wait_group %0;" :: "n"(N));
}

// ---------------------------------------------------------------------------
// QKV projection via tf32 tensor cores. K/V outputs pre-rounded to tf32.
// ---------------------------------------------------------------------------
__global__ __launch_bounds__(256) void qkv_gemm(
    const float* __restrict__ X,
    const float* __restrict__ Wq, const float* __restrict__ bq,
    const float* __restrict__ Wk, const float* __restrict__ bk,
    const float* __restrict__ Wv, const float* __restrict__ bv)
{
    const float* W;
    const float* bias;
    float* out;
    bool roundout;
    if (blockIdx.z == 0)      { W = Wq; bias = bq; out = g_Q; roundout = false; }
    else if (blockIdx.z == 1) { W = Wk; bias = bk; out = g_K; roundout = true; }
    else                      { W = Wv; bias = bv; out = g_V; roundout = true; }

    __shared__ float sA[2][128 * SAS];
    __shared__ float sB[2][16 * SBS];

    const int tid  = threadIdx.x;
    const int lane = tid & 31;
    const int warp = tid >> 5;
    const int g    = lane >> 2;
    const int t    = lane & 3;
    const int wm   = (warp & 3) * 32;
    const int wn   = (warp >> 2) * 64;

    const int bm = blockIdx.y * 128;
    const int bn = blockIdx.x * 128;

    float c[2][8][4];
#pragma unroll
    for (int mi = 0; mi < 2; mi++)
#pragma unroll
        for (int ni = 0; ni < 8; ni++)
#pragma unroll
            for (int r = 0; r < 4; r++) c[mi][ni][r] = 0.f;

    const uint32_t sAu = smem_u32(&sA[0][0]);
    const uint32_t sBu = smem_u32(&sB[0][0]);

    auto load_tile = [&](int st, int kt) {
        const uint32_t aBase = sAu + st * (128 * SAS * 4);
        const uint32_t bBase = sBu + st * (16 * SBS * 4);
#pragma unroll
        for (int j = 0; j < 2; j++) {
            const int ca = tid + 256 * j;
            const int m  = ca >> 2;
            const int k4 = (ca & 3) * 4;
            cp_async16(aBase + (m * SAS + k4) * 4,
                       X + (size_t)(bm + m) * HID + kt * 16 + k4);
            const int r  = ca >> 5;
            const int n4 = (ca & 31) * 4;
            cp_async16(bBase + (r * SBS + n4) * 4,
                       W + (size_t)(kt * 16 + r) * HID + bn + n4);
        }
        cp_commit();
    };

    load_tile(0, 0);

    int buf = 0;
#pragma unroll 1
    for (int kt = 0; kt < HID / 16; kt++) {
        if (kt + 1 < HID / 16) {
            load_tile(buf ^ 1, kt + 1);
            cp_wait<1>();
        } else {
            cp_wait<0>();
        }
        __syncthreads();

        const float* A = &sA[buf][0];
        const float* B = &sB[buf][0];
#pragma unroll
        for (int kk = 0; kk < 2; kk++) {
            const int k0 = kk * 8;
            unsigned a[2][4];
#pragma unroll
            for (int mi = 0; mi < 2; mi++) {
                const int row = wm + mi * 16 + g;
                a[mi][0] = f2tf(A[row * SAS + k0 + t]);
                a[mi][1] = f2tf(A[(row + 8) * SAS + k0 + t]);
                a[mi][2] = f2tf(A[row * SAS + k0 + t + 4]);
                a[mi][3] = f2tf(A[(row + 8) * SAS + k0 + t + 4]);
            }
#pragma unroll
            for (int ni = 0; ni < 8; ni++) {
                const int col = wn + ni * 8 + g;
                const unsigned b0 = f2tf(B[(k0 + t) * SBS + col]);
                const unsigned b1 = f2tf(B[(k0 + t + 4) * SBS + col]);
                mma_tf32(c[0][ni], a[0], b0, b1);
                mma_tf32(c[1][ni], a[1], b0, b1);
            }
        }
        __syncthreads();
        buf ^= 1;
    }

#pragma unroll
    for (int mi = 0; mi < 2; mi++) {
        const int row0 = bm + wm + mi * 16 + g;
#pragma unroll
        for (int ni = 0; ni < 8; ni++) {
            const int col = bn + wn + ni * 8 + 2 * t;
            const float bz0 = __ldg(bias + col);
            const float bz1 = __ldg(bias + col + 1);
            const int head = col >> 6;
            const int dcol = col & 63;
            float v00 = c[mi][ni][0] + bz0, v01 = c[mi][ni][1] + bz1;
            float v10 = c[mi][ni][2] + bz0, v11 = c[mi][ni][3] + bz1;
            if (roundout) {
                v00 = __uint_as_float(f2tf(v00));
                v01 = __uint_as_float(f2tf(v01));
                v10 = __uint_as_float(f2tf(v10));
                v11 = __uint_as_float(f2tf(v11));
            }
            *(float2*)(out + ((size_t)head * NB + row0) * DH + dcol) =
                make_float2(v00, v01);
            *(float2*)(out + ((size_t)head * NB + row0 + 8) * DH + dcol) =
                make_float2(v10, v11);
        }
    }
}

// ---------------------------------------------------------------------------
// Ak[h][i][w] = (sum_d Q[h][i][d] * Wrk[d][w]) * 0.125 * log2(e)
// Block = 128 threads = 128 query rows of one head. Wrk staged in smem;
// all lanes read the same Wrk element -> broadcast LDS (conflict-free).
// ---------------------------------------------------------------------------
__global__ __launch_bounds__(128) void ak_kernel(const float* __restrict__ Wrk)
{
    __shared__ float sW[DH][NSLOT + 1];   // 64 x 130 floats, 33.3KB

    const int h   = blockIdx.y;
    const int tid = threadIdx.x;
    const int i   = blockIdx.x * 128 + tid;

    for (int idx = tid; idx < DH * NSLOT; idx += 128) {
        const int d = idx / NSLOT;
        const int w = idx % NSLOT;
        sW[d][w] = Wrk[idx];
    }
    __syncthreads();

    float q[DH];
    {
        const float* Qr = g_Q + ((size_t)h * NB + i) * DH;
#pragma unroll
        for (int d4 = 0; d4 < 16; d4++) {
            float4 tq = ((const float4*)Qr)[d4];
            q[4*d4+0]=tq.x; q[4*d4+1]=tq.y; q[4*d4+2]=tq.z; q[4*d4+3]=tq.w;
        }
    }

    float* Ao = g_Ak + ((size_t)h * NB + i) * NSLOT;
    const float sc = 0.125f * LOG2E;

#pragma unroll 1
    for (int w = 0; w < NSLOT - 1; w += 2) {
        float s0 = 0.f, s1 = 0.f;
#pragma unroll
        for (int d = 0; d < DH; d++) {
            const float2 ww = *(const float2*)&sW[d][w];
            s0 = fmaf(q[d], ww.x, s0);
            s1 = fmaf(q[d], ww.y, s1);
        }
        Ao[w]     = s0 * sc;
        Ao[w + 1] = s1 * sc;
    }
    {
        float s0 = 0.f;
#pragma unroll
        for (int d = 0; d < DH; d++)
            s0 = fmaf(q[d], sW[d][NSLOT - 1], s0);
        Ao[NSLOT - 1] = s0 * sc;
    }
}

// ---------------------------------------------------------------------------
// Precompute masked-ext in log2 units
// ---------------------------------------------------------------------------
__global__ void ext_kernel(const float* __restrict__ mask)
{
    const int i = blockIdx.x * 256 + threadIdx.x;
    if (i < NB)
        g_Ext[i] = ((1.0f - mask[i]) * (-3.4028235e38f)) * LOG2E;
}

// ---------------------------------------------------------------------------
// Tensor-core flash attention. cp.async double-buffered K/V staging.
// QK MMA loop ordered kk-outer/n-inner for 8 independent accumulator chains.
// ---------------------------------------------------------------------------
__global__ __launch_bounds__(128) void attn_kernel(
    const float* __restrict__ Wrv, float* __restrict__ out)
{
    extern __shared__ float smem[];
    float* sK    = smem;                       // [2][64][SKP]
    float* sV    = sK + 2 * 64 * SKP;          // [2][64][SVP]
    float* sBand = sV + 2 * 64 * SVP;          // [64][SBP]
    float* sExt  = sBand + 64 * SBP;           // [2][64]

    const int tid  = threadIdx.x;
    const int lane = tid & 31;
    const int warp = tid >> 5;
    const int g    = lane >> 2;
    const int t    = lane & 3;

    const int h  = blockIdx.y;
    const int qt = blockIdx.x;
    const int row_lo = qt * 64 + warp * 16 + g;
    const int row_hi = row_lo + 8;
    const int il_lo_r = warp * 16 + g;
    const int il_hi_r = il_lo_r + 8;

    const float* Kg = g_K + (size_t)h * NB * DH;
    const float* Vg = g_V + (size_t)h * NB * DH;
    const float* AkB = g_Ak + (size_t)h * NB * NSLOT;

    const uint32_t sKu = smem_u32(sK);
    const uint32_t sVu = smem_u32(sV);
    const uint32_t sEu = smem_u32(sExt);

    auto load_tile = [&](int st, int kt) {
        const uint32_t kBase = sKu + st * (64 * SKP * 4);
        const uint32_t vBase = sVu + st * (64 * SVP * 4);
#pragma unroll
        for (int j = 0; j < 8; j++) {
            const int c   = tid + 128 * j;
            const int row = c >> 4;
            const int c4  = (c & 15) * 4;
            const float* src = Kg + ((size_t)kt * 64 + row) * DH + c4;
            cp_async16(kBase + (row * SKP + c4) * 4, src);
            const float* vsrc = Vg + ((size_t)kt * 64 + row) * DH + c4;
            cp_async16(vBase + (row * SVP + c4) * 4, vsrc);
        }
        if (tid < 16)
            cp_async16(sEu + st * 256 + tid * 16, g_Ext + kt * 64 + tid * 4);
        cp_commit();
    };

    unsigned qa[8][4];
    {
        const float* Qb = g_Q + (size_t)h * NB * DH;
        const float sc = 0.125f * LOG2E;
#pragma unroll
        for (int kk = 0; kk < 8; kk++) {
            qa[kk][0] = f2tf(Qb[(size_t)row_lo * DH + kk * 8 + t]     * sc);
            qa[kk][1] = f2tf(Qb[(size_t)row_hi * DH + kk * 8 + t]     * sc);
            qa[kk][2] = f2tf(Qb[(size_t)row_lo * DH + kk * 8 + t + 4] * sc);
            qa[kk][3] = f2tf(Qb[(size_t)row_hi * DH + kk * 8 + t + 4] * sc);
        }
    }

    float o[8][4];
#pragma unroll
    for (int n = 0; n < 8; n++)
#pragma unroll
        for (int r = 0; r < 4; r++) o[n][r] = 0.f;
    float m_lo = -1e30f, m_hi = -1e30f, l_lo = 0.f, l_hi = 0.f;

    for (int idx = tid; idx < 64 * SBP; idx += 128) sBand[idx] = -1e30f;

    load_tile(0, 0);
    load_tile(1, 1);

    int buf = 0;
#pragma unroll 1
    for (int kt = 0; kt < 32; kt++) {
        cp_wait<1>();
        __syncthreads();

        const float* K = sK + buf * (64 * SKP);
        const float* V = sV + buf * (64 * SVP);
        const float* E = sExt + buf * 64;

        // --- scores S = Q K^T: kk outer so the 8 n-MMAs are independent ---
        float s[8][4];
#pragma unroll
        for (int n = 0; n < 8; n++) {
            s[n][0] = s[n][1] = s[n][2] = s[n][3] = 0.f;
        }
#pragma unroll
        for (int kk = 0; kk < 8; kk++) {
#pragma unroll
            for (int n = 0; n < 8; n++) {
                unsigned b0 = __float_as_uint(K[(n * 8 + g) * SKP + kk * 8 + t]);
                unsigned b1 = __float_as_uint(K[(n * 8 + g) * SKP + kk * 8 + t + 4]);
                mma_tf32(s[n], qa[kk], b0, b1);
            }
        }

        // --- ext mask + relative-K bias + band stash ---
        const int jbase = kt * 64;
        const int qbase = qt * 64;
        const bool band_tile = (jbase >= qbase - 127) && (jbase <= qbase + 127);
#pragma unroll
        for (int n = 0; n < 8; n++) {
            const float e0 = E[n * 8 + 2 * t];
            const float e1 = E[n * 8 + 2 * t + 1];
            s[n][0] += e0; s[n][1] += e1;
            s[n][2] += e0; s[n][3] += e1;
            if (band_tile) {
                const int j0 = jbase + n * 8 + 2 * t;
                const int j1 = j0 + 1;
                int sl;
                sl = j0 - row_lo + WKW;
                if ((unsigned)sl <= 128u) {
                    s[n][0] += __ldg(AkB + (size_t)row_lo * NSLOT + sl);
                    sBand[il_lo_r * SBP + sl] = s[n][0];
                }
                sl = j1 - row_lo + WKW;
                if ((unsigned)sl <= 128u) {
                    s[n][1] += __ldg(AkB + (size_t)row_lo * NSLOT + sl);
                    sBand[il_lo_r * SBP + sl] = s[n][1];
                }
                sl = j0 - row_hi + WKW;
                if ((unsigned)sl <= 128u) {
                    s[n][2] += __ldg(AkB + (size_t)row_hi * NSLOT + sl);
                    sBand[il_hi_r * SBP + sl] = s[n][2];
                }
                sl = j1 - row_hi + WKW;
                if ((unsigned)sl <= 128u) {
                    s[n][3] += __ldg(AkB + (size_t)row_hi * NSLOT + sl);
                    sBand[il_hi_r * SBP + sl] = s[n][3];
                }
            }
        }

        // --- online softmax ---
        float tm_lo = -1e30f, tm_hi = -1e30f;
#pragma unroll
        for (int n = 0; n < 8; n++) {
            tm_lo = fmaxf(tm_lo, fmaxf(s[n][0], s[n][1]));
            tm_hi = fmaxf(tm_hi, fmaxf(s[n][2], s[n][3]));
        }
        tm_lo = fmaxf(tm_lo, __shfl_xor_sync(0xffffffffu, tm_lo, 1));
        tm_lo = fmaxf(tm_lo, __shfl_xor_sync(0xffffffffu, tm_lo, 2));
        tm_hi = fmaxf(tm_hi, __shfl_xor_sync(0xffffffffu, tm_hi, 1));
        tm_hi = fmaxf(tm_hi, __shfl_xor_sync(0xffffffffu, tm_hi, 2));
        const float mn_lo = fmaxf(m_lo, tm_lo);
        const float mn_hi = fmaxf(m_hi, tm_hi);
        const float sc_lo = fexp2(m_lo - mn_lo);
        const float sc_hi = fexp2(m_hi - mn_hi);
        l_lo *= sc_lo;
        l_hi *= sc_hi;
#pragma unroll
        for (int n = 0; n < 8; n++) {
            o[n][0] *= sc_lo; o[n][1] *= sc_lo;
            o[n][2] *= sc_hi; o[n][3] *= sc_hi;
        }
        m_lo = mn_lo; m_hi = mn_hi;

        unsigned pb[8][4];
#pragma unroll
        for (int n = 0; n < 8; n++) {
            const float p0 = fexp2(s[n][0] - m_lo);
            const float p1 = fexp2(s[n][1] - m_lo);
            const float p2 = fexp2(s[n][2] - m_hi);
            const float p3 = fexp2(s[n][3] - m_hi);
            l_lo += p0 + p1;
            l_hi += p2 + p3;
            pb[n][0] = f2tf(p0); pb[n][1] = f2tf(p1);
            pb[n][2] = f2tf(p2); pb[n][3] = f2tf(p3);
        }

        // --- PV ---
        const int srcA = (lane & ~3) | (t >> 1);
        const int srcB = srcA + 2;
#pragma unroll
        for (int kk = 0; kk < 8; kk++) {
            unsigned pa[4];
            unsigned u0 = __shfl_sync(0xffffffffu, pb[kk][0], srcA);
            unsigned u1 = __shfl_sync(0xffffffffu, pb[kk][1], srcA);
            unsigned v0 = __shfl_sync(0xffffffffu, pb[kk][0], srcB);
            unsigned v1 = __shfl_sync(0xffffffffu, pb[kk][1], srcB);
            pa[0] = (t & 1) ? u1 : u0;
            pa[2] = (t & 1) ? v1 : v0;
            u0 = __shfl_sync(0xffffffffu, pb[kk][2], srcA);
            u1 = __shfl_sync(0xffffffffu, pb[kk][3], srcA);
            v0 = __shfl_sync(0xffffffffu, pb[kk][2], srcB);
            v1 = __shfl_sync(0xffffffffu, pb[kk][3], srcB);
            pa[1] = (t & 1) ? u1 : u0;
            pa[3] = (t & 1) ? v1 : v0;
#pragma unroll
            for (int n = 0; n < 8; n++) {
                unsigned b0 = __float_as_uint(V[(kk * 8 + t)     * SVP + n * 8 + g]);
                unsigned b1 = __float_as_uint(V[(kk * 8 + t + 4) * SVP + n * 8 + g]);
                mma_tf32(o[n], pa, b0, b1);
            }
        }

        __syncthreads();
        if (kt + 2 < 32) load_tile(buf, kt + 2);
        else             cp_commit();
        buf ^= 1;
    }

    l_lo += __shfl_xor_sync(0xffffffffu, l_lo, 1);
    l_lo += __shfl_xor_sync(0xffffffffu, l_lo, 2);
    l_hi += __shfl_xor_sync(0xffffffffu, l_hi, 1);
    l_hi += __shfl_xor_sync(0xffffffffu, l_hi, 2);
    __syncwarp();

    // --- band epilogue GEMM ---
#pragma unroll 1
    for (int kk = 0; kk < 17; kk++) {
        const int k0 = kk * 8;
        unsigned a[4];
        a[0] = f2tf(fexp2(sBand[il_lo_r * SBP + k0 + t]     - m_lo));
        a[1] = f2tf(fexp2(sBand[il_hi_r * SBP + k0 + t]     - m_hi));
        a[2] = f2tf(fexp2(sBand[il_lo_r * SBP + k0 + t + 4] - m_lo));
        a[3] = f2tf(fexp2(sBand[il_hi_r * SBP + k0 + t + 4] - m_hi));
        const int sl0 = k0 + t, sl1 = k0 + t + 4;
#pragma unroll
        for (int n = 0; n < 8; n++) {
            const int d = n * 8 + g;
            float w0 = (sl0 < NSLOT) ? __ldg(Wrv + (size_t)sl0 * DH + d) : 0.f;
            float w1 = (sl1 < NSLOT) ? __ldg(Wrv + (size_t)sl1 * DH + d) : 0.f;
            mma_tf32(o[n], a, f2tf(w0), f2tf(w1));
        }
    }

    const float inl = 1.0f / l_lo;
    const float inh = 1.0f / l_hi;
    float* out_lo = out + (size_t)row_lo * HID + h * DH;
    float* out_hi = out + (size_t)row_hi * HID + h * DH;
#pragma unroll
    for (int n = 0; n < 8; n++) {
        float2 w0 = make_float2(o[n][0] * inl, o[n][1] * inl);
        float2 w1 = make_float2(o[n][2] * inh, o[n][3] * inh);
        *(float2*)(out_lo + n * 8 + 2 * t) = w0;
        *(float2*)(out_hi + n * 8 + 2 * t) = w1;
    }
}

// ---------------------------------------------------------------------------
// Launch
// ---------------------------------------------------------------------------
extern "C" void kernel_launch(void* const* d_in, const int* in_sizes, int n_in,
                              void* d_out, int out_size)
{
    const float* X    = (const float*)d_in[0];
    const float* mask = (const float*)d_in[1];
    const float* Wq   = (const float*)d_in[2];
    const float* bq   = (const float*)d_in[3];
    const float* Wk   = (const float*)d_in[4];
    const float* bk   = (const float*)d_in[5];
    const float* Wv   = (const float*)d_in[6];
    const float* bv   = (const float*)d_in[7];
    const float* Wrk  = (const float*)d_in[8];
    const float* Wrv  = (const float*)d_in[9];
    float* out = (float*)d_out;

    const int smem_bytes =
        (2 * 64 * SKP + 2 * 64 * SVP + 64 * SBP + 2 * 64) * 4;
    static bool configured = false;
    if (!configured) {
        cudaFuncSetAttribute(attn_kernel,
                             cudaFuncAttributeMaxDynamicSharedMemorySize,
                             smem_bytes);
        configured = true;
    }

    dim3 gg(HID / 128, NB / 128, 3);
    qkv_gemm<<<gg, 256>>>(X, Wq, bq, Wk, bk, Wv, bv);

    ak_kernel<<<dim3(NB / 128, NH), 128>>>(Wrk);
    ext_kernel<<<NB / 256, 256>>>(mask);

    attn_kernel<<<dim3(NB / 64, NH), 128, smem_bytes>>>(Wrv, out);
}

// round 15
// speedup vs baseline: 1.5493x; 1.5493x over previous
#include <cuda_runtime.h>
#include <cstdint>

// ---------------------------------------------------------------------------
// Problem constants
// ---------------------------------------------------------------------------
#define NB   2048
#define HID  1024
#define NH   16
#define DH   64
#define WKW  64
#define NSLOT 129
#define LOG2E 1.44269504f

// attn smem pads
#define SKP 68
#define SVP 72
#define SBP 136

// qkv gemm smem strides (floats)
#define SAS 20
#define SBS 136

// ---------------------------------------------------------------------------
// Device scratch
// ---------------------------------------------------------------------------
__device__ float g_Q[NH * NB * DH];      // [h][n][d] exact fp32
__device__ float g_K[NH * NB * DH];      // [h][n][d] tf32-rounded bits
__device__ float g_V[NH * NB * DH];      // [h][n][d] tf32-rounded bits
__device__ float g_Ak[NH * NB * NSLOT]; // scaled relative-K bias [h][n][slot]
__device__ float g_Ext[NB];             // (1-mask)*NEG_BIG*LOG2E

// ---------------------------------------------------------------------------
// Helpers
// ---------------------------------------------------------------------------
__device__ __forceinline__ unsigned f2tf(float x) {
    unsigned u;
    asm("cvt.rna.tf32.f32 %0, %1;" : "=r"(u) : "f"(x));
    return u;
}
__device__ __forceinline__ float fexp2(float x) {
    float y;
    asm("ex2.approx.ftz.f32 %0, %1;" : "=f"(y) : "f"(x));
    return y;
}
__device__ __forceinline__ void mma_tf32(float c[4], const unsigned a[4],
                                         unsigned b0, unsigned b1) {
    asm volatile(
        "mma.sync.aligned.m16n8k8.row.col.f32.tf32.tf32.f32 "
        "{%0,%1,%2,%3},{%4,%5,%6,%7},{%8,%9},{%0,%1,%2,%3};"
        : "+f"(c[0]), "+f"(c[1]), "+f"(c[2]), "+f"(c[3])
        : "r"(a[0]), "r"(a[1]), "r"(a[2]), "r"(a[3]), "r"(b0), "r"(b1));
}
__device__ __forceinline__ uint32_t smem_u32(const void* p) {
    uint32_t a;
    asm("{ .reg .u64 t; cvta.to.shared.u64 t, %1; cvt.u32.u64 %0, t; }"
        : "=r"(a) : "l"(p));
    return a;
}
__device__ __forceinline__ void cp_async16(uint32_t s, const void* g) {
    asm volatile("cp.async.cg.shared.global [%0], [%1], 16;" :: "r"(s), "l"(g));
}
__device__ __forceinline__ void cp_commit() {
    asm volatile("cp.async.commit_group;");
}
template <int N>
__device__ __forceinline__ void cp_wait() {
    asm volatile("cp.async.wait_group %0;" :: "n"(N));
}

// ---------------------------------------------------------------------------
// QKV projection via tf32 tensor cores. K/V outputs pre-rounded to tf32.
// ---------------------------------------------------------------------------
__global__ __launch_bounds__(256) void qkv_gemm(
    const float* __restrict__ X,
    const float* __restrict__ Wq, const float* __restrict__ bq,
    const float* __restrict__ Wk, const float* __restrict__ bk,
    const float* __restrict__ Wv, const float* __restrict__ bv)
{
    const float* W;
    const float* bias;
    float* out;
    bool roundout;
    if (blockIdx.z == 0)      { W = Wq; bias = bq; out = g_Q; roundout = false; }
    else if (blockIdx.z == 1) { W = Wk; bias = bk; out = g_K; roundout = true; }
    else                      { W = Wv; bias = bv; out = g_V; roundout = true; }

    __shared__ float sA[2][128 * SAS];
    __shared__ float sB[2][16 * SBS];

    const int tid  = threadIdx.x;
    const int lane = tid & 31;
    const int warp = tid >> 5;
    const int g    = lane >> 2;
    const int t    = lane & 3;
    const int wm   = (warp & 3) * 32;
    const int wn   = (warp >> 2) * 64;

    const int bm = blockIdx.y * 128;
    const int bn = blockIdx.x * 128;

    float c[2][8][4];
#pragma unroll
    for (int mi = 0; mi < 2; mi++)
#pragma unroll
        for (int ni = 0; ni < 8; ni++)
#pragma unroll
            for (int r = 0; r < 4; r++) c[mi][ni][r] = 0.f;

    const uint32_t sAu = smem_u32(&sA[0][0]);
    const uint32_t sBu = smem_u32(&sB[0][0]);

    auto load_tile = [&](int st, int kt) {
        const uint32_t aBase = sAu + st * (128 * SAS * 4);
        const uint32_t bBase = sBu + st * (16 * SBS * 4);
#pragma unroll
        for (int j = 0; j < 2; j++) {
            const int ca = tid + 256 * j;
            const int m  = ca >> 2;
            const int k4 = (ca & 3) * 4;
            cp_async16(aBase + (m * SAS + k4) * 4,
                       X + (size_t)(bm + m) * HID + kt * 16 + k4);
            const int r  = ca >> 5;
            const int n4 = (ca & 31) * 4;
            cp_async16(bBase + (r * SBS + n4) * 4,
                       W + (size_t)(kt * 16 + r) * HID + bn + n4);
        }
        cp_commit();
    };

    load_tile(0, 0);

    int buf = 0;
#pragma unroll 1
    for (int kt = 0; kt < HID / 16; kt++) {
        if (kt + 1 < HID / 16) {
            load_tile(buf ^ 1, kt + 1);
            cp_wait<1>();
        } else {
            cp_wait<0>();
        }
        __syncthreads();

        const float* A = &sA[buf][0];
        const float* B = &sB[buf][0];
#pragma unroll
        for (int kk = 0; kk < 2; kk++) {
            const int k0 = kk * 8;
            unsigned a[2][4];
#pragma unroll
            for (int mi = 0; mi < 2; mi++) {
                const int row = wm + mi * 16 + g;
                a[mi][0] = f2tf(A[row * SAS + k0 + t]);
                a[mi][1] = f2tf(A[(row + 8) * SAS + k0 + t]);
                a[mi][2] = f2tf(A[row * SAS + k0 + t + 4]);
                a[mi][3] = f2tf(A[(row + 8) * SAS + k0 + t + 4]);
            }
#pragma unroll
            for (int ni = 0; ni < 8; ni++) {
                const int col = wn + ni * 8 + g;
                const unsigned b0 = f2tf(B[(k0 + t) * SBS + col]);
                const unsigned b1 = f2tf(B[(k0 + t + 4) * SBS + col]);
                mma_tf32(c[0][ni], a[0], b0, b1);
                mma_tf32(c[1][ni], a[1], b0, b1);
            }
        }
        __syncthreads();
        buf ^= 1;
    }

#pragma unroll
    for (int mi = 0; mi < 2; mi++) {
        const int row0 = bm + wm + mi * 16 + g;
#pragma unroll
        for (int ni = 0; ni < 8; ni++) {
            const int col = bn + wn + ni * 8 + 2 * t;
            const float bz0 = __ldg(bias + col);
            const float bz1 = __ldg(bias + col + 1);
            const int head = col >> 6;
            const int dcol = col & 63;
            float v00 = c[mi][ni][0] + bz0, v01 = c[mi][ni][1] + bz1;
            float v10 = c[mi][ni][2] + bz0, v11 = c[mi][ni][3] + bz1;
            if (roundout) {
                v00 = __uint_as_float(f2tf(v00));
                v01 = __uint_as_float(f2tf(v01));
                v10 = __uint_as_float(f2tf(v10));
                v11 = __uint_as_float(f2tf(v11));
            }
            *(float2*)(out + ((size_t)head * NB + row0) * DH + dcol) =
                make_float2(v00, v01);
            *(float2*)(out + ((size_t)head * NB + row0 + 8) * DH + dcol) =
                make_float2(v10, v11);
        }
    }
}

// ---------------------------------------------------------------------------
// Ak[h][i][w] = (sum_d Q[h][i][d] * Wrk[d][w]) * 0.125 * log2(e)
// Block = 128 threads = 128 query rows of one head. Wrk staged in smem;
// all lanes read the same Wrk element -> broadcast LDS (conflict-free).
// ---------------------------------------------------------------------------
__global__ __launch_bounds__(128) void ak_kernel(const float* __restrict__ Wrk)
{
    __shared__ float sW[DH][NSLOT + 1];   // 64 x 130 floats

    const int h   = blockIdx.y;
    const int tid = threadIdx.x;
    const int i   = blockIdx.x * 128 + tid;

    for (int idx = tid; idx < DH * NSLOT; idx += 128) {
        const int d = idx / NSLOT;
        const int w = idx % NSLOT;
        sW[d][w] = Wrk[idx];
    }
    __syncthreads();

    float q[DH];
    {
        const float* Qr = g_Q + ((size_t)h * NB + i) * DH;
#pragma unroll
        for (int d4 = 0; d4 < 16; d4++) {
            float4 tq = ((const float4*)Qr)[d4];
            q[4*d4+0]=tq.x; q[4*d4+1]=tq.y; q[4*d4+2]=tq.z; q[4*d4+3]=tq.w;
        }
    }

    float* Ao = g_Ak + ((size_t)h * NB + i) * NSLOT;
    const float sc = 0.125f * LOG2E;

#pragma unroll 1
    for (int w = 0; w < NSLOT - 1; w += 2) {
        float s0 = 0.f, s1 = 0.f;
#pragma unroll
        for (int d = 0; d < DH; d++) {
            const float2 ww = *(const float2*)&sW[d][w];
            s0 = fmaf(q[d], ww.x, s0);
            s1 = fmaf(q[d], ww.y, s1);
        }
        Ao[w]     = s0 * sc;
        Ao[w + 1] = s1 * sc;
    }
    {
        float s0 = 0.f;
#pragma unroll
        for (int d = 0; d < DH; d++)
            s0 = fmaf(q[d], sW[d][NSLOT - 1], s0);
        Ao[NSLOT - 1] = s0 * sc;
    }
}

// ---------------------------------------------------------------------------
// Precompute masked-ext in log2 units
// ---------------------------------------------------------------------------
__global__ void ext_kernel(const float* __restrict__ mask)
{
    const int i = blockIdx.x * 256 + threadIdx.x;
    if (i < NB)
        g_Ext[i] = ((1.0f - mask[i]) * (-3.4028235e38f)) * LOG2E;
}

// ---------------------------------------------------------------------------
// Tensor-core flash attention. cp.async double-buffered K/V staging.
// QK MMA loop: n-outer / kk-inner (R8 ordering — measured fastest).
// ---------------------------------------------------------------------------
__global__ __launch_bounds__(128) void attn_kernel(
    const float* __restrict__ Wrv, float* __restrict__ out)
{
    extern __shared__ float smem[];
    float* sK    = smem;                       // [2][64][SKP]
    float* sV    = sK + 2 * 64 * SKP;          // [2][64][SVP]
    float* sBand = sV + 2 * 64 * SVP;          // [64][SBP]
    float* sExt  = sBand + 64 * SBP;           // [2][64]

    const int tid  = threadIdx.x;
    const int lane = tid & 31;
    const int warp = tid >> 5;
    const int g    = lane >> 2;
    const int t    = lane & 3;

    const int h  = blockIdx.y;
    const int qt = blockIdx.x;
    const int row_lo = qt * 64 + warp * 16 + g;
    const int row_hi = row_lo + 8;
    const int il_lo_r = warp * 16 + g;
    const int il_hi_r = il_lo_r + 8;

    const float* Kg = g_K + (size_t)h * NB * DH;
    const float* Vg = g_V + (size_t)h * NB * DH;
    const float* AkB = g_Ak + (size_t)h * NB * NSLOT;

    const uint32_t sKu = smem_u32(sK);
    const uint32_t sVu = smem_u32(sV);
    const uint32_t sEu = smem_u32(sExt);

    auto load_tile = [&](int st, int kt) {
        const uint32_t kBase = sKu + st * (64 * SKP * 4);
        const uint32_t vBase = sVu + st * (64 * SVP * 4);
#pragma unroll
        for (int j = 0; j < 8; j++) {
            const int c   = tid + 128 * j;
            const int row = c >> 4;
            const int c4  = (c & 15) * 4;
            const float* src = Kg + ((size_t)kt * 64 + row) * DH + c4;
            cp_async16(kBase + (row * SKP + c4) * 4, src);
            const float* vsrc = Vg + ((size_t)kt * 64 + row) * DH + c4;
            cp_async16(vBase + (row * SVP + c4) * 4, vsrc);
        }
        if (tid < 16)
            cp_async16(sEu + st * 256 + tid * 16, g_Ext + kt * 64 + tid * 4);
        cp_commit();
    };

    unsigned qa[8][4];
    {
        const float* Qb = g_Q + (size_t)h * NB * DH;
        const float sc = 0.125f * LOG2E;
#pragma unroll
        for (int kk = 0; kk < 8; kk++) {
            qa[kk][0] = f2tf(Qb[(size_t)row_lo * DH + kk * 8 + t]     * sc);
            qa[kk][1] = f2tf(Qb[(size_t)row_hi * DH + kk * 8 + t]     * sc);
            qa[kk][2] = f2tf(Qb[(size_t)row_lo * DH + kk * 8 + t + 4] * sc);
            qa[kk][3] = f2tf(Qb[(size_t)row_hi * DH + kk * 8 + t + 4] * sc);
        }
    }

    float o[8][4];
#pragma unroll
    for (int n = 0; n < 8; n++)
#pragma unroll
        for (int r = 0; r < 4; r++) o[n][r] = 0.f;
    float m_lo = -1e30f, m_hi = -1e30f, l_lo = 0.f, l_hi = 0.f;

    for (int idx = tid; idx < 64 * SBP; idx += 128) sBand[idx] = -1e30f;

    load_tile(0, 0);
    load_tile(1, 1);

    int buf = 0;
#pragma unroll 1
    for (int kt = 0; kt < 32; kt++) {
        cp_wait<1>();
        __syncthreads();

        const float* K = sK + buf * (64 * SKP);
        const float* V = sV + buf * (64 * SVP);
        const float* E = sExt + buf * 64;

        // --- scores S = Q K^T ---
        float s[8][4];
#pragma unroll
        for (int n = 0; n < 8; n++) {
            s[n][0] = s[n][1] = s[n][2] = s[n][3] = 0.f;
#pragma unroll
            for (int kk = 0; kk < 8; kk++) {
                unsigned b0 = __float_as_uint(K[(n * 8 + g) * SKP + kk * 8 + t]);
                unsigned b1 = __float_as_uint(K[(n * 8 + g) * SKP + kk * 8 + t + 4]);
                mma_tf32(s[n], qa[kk], b0, b1);
            }
        }

        // --- ext mask + relative-K bias + band stash ---
        const int jbase = kt * 64;
        const int qbase = qt * 64;
        const bool band_tile = (jbase >= qbase - 127) && (jbase <= qbase + 127);
#pragma unroll
        for (int n = 0; n < 8; n++) {
            const float e0 = E[n * 8 + 2 * t];
            const float e1 = E[n * 8 + 2 * t + 1];
            s[n][0] += e0; s[n][1] += e1;
            s[n][2] += e0; s[n][3] += e1;
            if (band_tile) {
                const int j0 = jbase + n * 8 + 2 * t;
                const int j1 = j0 + 1;
                int sl;
                sl = j0 - row_lo + WKW;
                if ((unsigned)sl <= 128u) {
                    s[n][0] += __ldg(AkB + (size_t)row_lo * NSLOT + sl);
                    sBand[il_lo_r * SBP + sl] = s[n][0];
                }
                sl = j1 - row_lo + WKW;
                if ((unsigned)sl <= 128u) {
                    s[n][1] += __ldg(AkB + (size_t)row_lo * NSLOT + sl);
                    sBand[il_lo_r * SBP + sl] = s[n][1];
                }
                sl = j0 - row_hi + WKW;
                if ((unsigned)sl <= 128u) {
                    s[n][2] += __ldg(AkB + (size_t)row_hi * NSLOT + sl);
                    sBand[il_hi_r * SBP + sl] = s[n][2];
                }
                sl = j1 - row_hi + WKW;
                if ((unsigned)sl <= 128u) {
                    s[n][3] += __ldg(AkB + (size_t)row_hi * NSLOT + sl);
                    sBand[il_hi_r * SBP + sl] = s[n][3];
                }
            }
        }

        // --- online softmax ---
        float tm_lo = -1e30f, tm_hi = -1e30f;
#pragma unroll
        for (int n = 0; n < 8; n++) {
            tm_lo = fmaxf(tm_lo, fmaxf(s[n][0], s[n][1]));
            tm_hi = fmaxf(tm_hi, fmaxf(s[n][2], s[n][3]));
        }
        tm_lo = fmaxf(tm_lo, __shfl_xor_sync(0xffffffffu, tm_lo, 1));
        tm_lo = fmaxf(tm_lo, __shfl_xor_sync(0xffffffffu, tm_lo, 2));
        tm_hi = fmaxf(tm_hi, __shfl_xor_sync(0xffffffffu, tm_hi, 1));
        tm_hi = fmaxf(tm_hi, __shfl_xor_sync(0xffffffffu, tm_hi, 2));
        const float mn_lo = fmaxf(m_lo, tm_lo);
        const float mn_hi = fmaxf(m_hi, tm_hi);
        const float sc_lo = fexp2(m_lo - mn_lo);
        const float sc_hi = fexp2(m_hi - mn_hi);
        l_lo *= sc_lo;
        l_hi *= sc_hi;
#pragma unroll
        for (int n = 0; n < 8; n++) {
            o[n][0] *= sc_lo; o[n][1] *= sc_lo;
            o[n][2] *= sc_hi; o[n][3] *= sc_hi;
        }
        m_lo = mn_lo; m_hi = mn_hi;

        unsigned pb[8][4];
#pragma unroll
        for (int n = 0; n < 8; n++) {
            const float p0 = fexp2(s[n][0] - m_lo);
            const float p1 = fexp2(s[n][1] - m_lo);
            const float p2 = fexp2(s[n][2] - m_hi);
            const float p3 = fexp2(s[n][3] - m_hi);
            l_lo += p0 + p1;
            l_hi += p2 + p3;
            pb[n][0] = f2tf(p0); pb[n][1] = f2tf(p1);
            pb[n][2] = f2tf(p2); pb[n][3] = f2tf(p3);
        }

        // --- PV ---
        const int srcA = (lane & ~3) | (t >> 1);
        const int srcB = srcA + 2;
#pragma unroll
        for (int kk = 0; kk < 8; kk++) {
            unsigned pa[4];
            unsigned u0 = __shfl_sync(0xffffffffu, pb[kk][0], srcA);
            unsigned u1 = __shfl_sync(0xffffffffu, pb[kk][1], srcA);
            unsigned v0 = __shfl_sync(0xffffffffu, pb[kk][0], srcB);
            unsigned v1 = __shfl_sync(0xffffffffu, pb[kk][1], srcB);
            pa[0] = (t & 1) ? u1 : u0;
            pa[2] = (t & 1) ? v1 : v0;
            u0 = __shfl_sync(0xffffffffu, pb[kk][2], srcA);
            u1 = __shfl_sync(0xffffffffu, pb[kk][3], srcA);
            v0 = __shfl_sync(0xffffffffu, pb[kk][2], srcB);
            v1 = __shfl_sync(0xffffffffu, pb[kk][3], srcB);
            pa[1] = (t & 1) ? u1 : u0;
            pa[3] = (t & 1) ? v1 : v0;
#pragma unroll
            for (int n = 0; n < 8; n++) {
                unsigned b0 = __float_as_uint(V[(kk * 8 + t)     * SVP + n * 8 + g]);
                unsigned b1 = __float_as_uint(V[(kk * 8 + t + 4) * SVP + n * 8 + g]);
                mma_tf32(o[n], pa, b0, b1);
            }
        }

        __syncthreads();
        if (kt + 2 < 32) load_tile(buf, kt + 2);
        else             cp_commit();
        buf ^= 1;
    }

    l_lo += __shfl_xor_sync(0xffffffffu, l_lo, 1);
    l_lo += __shfl_xor_sync(0xffffffffu, l_lo, 2);
    l_hi += __shfl_xor_sync(0xffffffffu, l_hi, 1);
    l_hi += __shfl_xor_sync(0xffffffffu, l_hi, 2);
    __syncwarp();

    // --- band epilogue GEMM ---
#pragma unroll 1
    for (int kk = 0; kk < 17; kk++) {
        const int k0 = kk * 8;
        unsigned a[4];
        a[0] = f2tf(fexp2(sBand[il_lo_r * SBP + k0 + t]     - m_lo));
        a[1] = f2tf(fexp2(sBand[il_hi_r * SBP + k0 + t]     - m_hi));
        a[2] = f2tf(fexp2(sBand[il_lo_r * SBP + k0 + t + 4] - m_lo));
        a[3] = f2tf(fexp2(sBand[il_hi_r * SBP + k0 + t + 4] - m_hi));
        const int sl0 = k0 + t, sl1 = k0 + t + 4;
#pragma unroll
        for (int n = 0; n < 8; n++) {
            const int d = n * 8 + g;
            float w0 = (sl0 < NSLOT) ? __ldg(Wrv + (size_t)sl0 * DH + d) : 0.f;
            float w1 = (sl1 < NSLOT) ? __ldg(Wrv + (size_t)sl1 * DH + d) : 0.f;
            mma_tf32(o[n], a, f2tf(w0), f2tf(w1));
        }
    }

    const float inl = 1.0f / l_lo;
    const float inh = 1.0f / l_hi;
    float* out_lo = out + (size_t)row_lo * HID + h * DH;
    float* out_hi = out + (size_t)row_hi * HID + h * DH;
#pragma unroll
    for (int n = 0; n < 8; n++) {
        float2 w0 = make_float2(o[n][0] * inl, o[n][1] * inl);
        float2 w1 = make_float2(o[n][2] * inh, o[n][3] * inh);
        *(float2*)(out_lo + n * 8 + 2 * t) = w0;
        *(float2*)(out_hi + n * 8 + 2 * t) = w1;
    }
}

// ---------------------------------------------------------------------------
// Launch
// ---------------------------------------------------------------------------
extern "C" void kernel_launch(void* const* d_in, const int* in_sizes, int n_in,
                              void* d_out, int out_size)
{
    const float* X    = (const float*)d_in[0];
    const float* mask = (const float*)d_in[1];
    const float* Wq   = (const float*)d_in[2];
    const float* bq   = (const float*)d_in[3];
    const float* Wk   = (const float*)d_in[4];
    const float* bk   = (const float*)d_in[5];
    const float* Wv   = (const float*)d_in[6];
    const float* bv   = (const float*)d_in[7];
    const float* Wrk  = (const float*)d_in[8];
    const float* Wrv  = (const float*)d_in[9];
    float* out = (float*)d_out;

    const int smem_bytes =
        (2 * 64 * SKP + 2 * 64 * SVP + 64 * SBP + 2 * 64) * 4;
    cudaFuncSetAttribute(attn_kernel,
                         cudaFuncAttributeMaxDynamicSharedMemorySize,
                         smem_bytes);

    dim3 gg(HID / 128, NB / 128, 3);
    qkv_gemm<<<gg, 256>>>(X, Wq, bq, Wk, bk, Wv, bv);

    ak_kernel<<<dim3(NB / 128, NH), 128>>>(Wrk);
    ext_kernel<<<NB / 256, 256>>>(mask);

    attn_kernel<<<dim3(NB / 64, NH), 128, smem_bytes>>>(Wrv, out);
}